// round 1
// baseline (speedup 1.0000x reference)
#include <cuda_runtime.h>
#include <math.h>

// QNN_37726992728716 — 21-qubit, 3-layer variational circuit statevector sim.
//
// Flat-index bit k corresponds to qubit (20-k). Per layer:
//   Rot on every qubit, then CNOT pairs (c=b+1, t=b) for odd b (even sublayer),
//   then for even b (odd sublayer).
// Split each layer into:
//   pass A: gates on bits 0..10   (Rot 0-10; CNOT targets {1,3,5,7,9} / {0,2,4,6,8})
//   pass B: gates on bits 10..20  (Rot 11-20; CNOT targets {11,13,15,17,19} / {10,12,14,16,18})
// CNOT sublayers fold into a single index permutation applied at the smem->gmem store.

#define NQ       21
#define NSTATE   (1u << NQ)
#define THREADS  512
#define TILE     8192              // 2^13 amplitudes per block
#define SMEMB    (TILE * 8)        // 64 KB dynamic shared
#define NBLK     256               // 2^21 / 2^13

__device__ float2 d_state[NSTATE];
__device__ float  d_partials[NBLK];

struct RotU { float2 u00, u01, u10, u11; };

__device__ __forceinline__ RotU rot_for(const float* __restrict__ param, int layer, int bit) {
    const int qubit = 20 - bit;
    const float* p = param + (layer * NQ + qubit) * 3;
    const float phi = p[0], th = p[1], om = p[2];
    float s, c;   sincosf(0.5f * th, &s, &c);
    float sa, ca; sincosf(0.5f * (phi + om), &sa, &ca);   // ep = (ca, -sa)
    float sb, cb; sincosf(0.5f * (phi - om), &sb, &cb);   // em = (cb,  sb)
    RotU u;
    u.u00 = make_float2( ca * c, -sa * c);   // ep*c
    u.u01 = make_float2(-cb * s, -sb * s);   // -em*s
    u.u10 = make_float2( cb * s, -sb * s);   // conj(em)*s
    u.u11 = make_float2( ca * c,  sa * c);   // conj(ep)*c
    return u;
}

// Apply 2x2 gate pairing register indices that differ in bit S of j (16 amps/thread).
template<int S>
__device__ __forceinline__ void apply_rot(float2 a[16], const RotU u) {
#pragma unroll
    for (int j = 0; j < 16; j++) {
        if (j & (1 << S)) continue;
        const int j1 = j | (1 << S);
        const float2 x = a[j], y = a[j1];
        a[j]  = make_float2(u.u00.x * x.x - u.u00.y * x.y + u.u01.x * y.x - u.u01.y * y.y,
                            u.u00.x * x.y + u.u00.y * x.x + u.u01.x * y.y + u.u01.y * y.x);
        a[j1] = make_float2(u.u10.x * x.x - u.u10.y * x.y + u.u11.x * y.x - u.u11.y * y.y,
                            u.u10.x * x.y + u.u10.y * x.x + u.u11.x * y.y + u.u11.y * y.x);
    }
}

// ---------------- pass A: tile = global bits 0..12 (gates on 0..10) ----------------
template<int LAYER, bool FIRST>
__global__ void __launch_bounds__(THREADS)
passA_kernel(const float* __restrict__ feat, const float* __restrict__ param) {
    extern __shared__ float2 tile[];
    const unsigned tid   = threadIdx.x;
    const unsigned gbase = blockIdx.x << 13;
    float2 a[16];

    // round 1: bits 0-3, straight from global (coalesced float4)
    {
        const unsigned base = tid << 4;
        if (FIRST) {
            const float4* f4 = reinterpret_cast<const float4*>(feat + gbase + base);
#pragma unroll
            for (int q = 0; q < 4; q++) {
                float4 v = f4[q];
                a[q * 4 + 0] = make_float2(v.x, 0.f);
                a[q * 4 + 1] = make_float2(v.y, 0.f);
                a[q * 4 + 2] = make_float2(v.z, 0.f);
                a[q * 4 + 3] = make_float2(v.w, 0.f);
            }
        } else {
            const float4* s4 = reinterpret_cast<const float4*>(d_state + gbase + base);
#pragma unroll
            for (int q = 0; q < 8; q++) {
                float4 v = s4[q];
                a[q * 2 + 0] = make_float2(v.x, v.y);
                a[q * 2 + 1] = make_float2(v.z, v.w);
            }
        }
        apply_rot<0>(a, rot_for(param, LAYER, 0));
        apply_rot<1>(a, rot_for(param, LAYER, 1));
        apply_rot<2>(a, rot_for(param, LAYER, 2));
        apply_rot<3>(a, rot_for(param, LAYER, 3));
#pragma unroll
        for (int j = 0; j < 16; j++) tile[base + j] = a[j];
    }
    __syncthreads();

    // round 2: bits 4-7 (each thread owns its 16 slots — no intra-round sync)
    {
        const unsigned base = ((tid & ~15u) << 4) | (tid & 15u);
#pragma unroll
        for (int j = 0; j < 16; j++) a[j] = tile[base | (j << 4)];
        apply_rot<0>(a, rot_for(param, LAYER, 4));
        apply_rot<1>(a, rot_for(param, LAYER, 5));
        apply_rot<2>(a, rot_for(param, LAYER, 6));
        apply_rot<3>(a, rot_for(param, LAYER, 7));
#pragma unroll
        for (int j = 0; j < 16; j++) tile[base | (j << 4)] = a[j];
    }
    __syncthreads();

    // round 3: bits 8-11 (gates on 8,9,10; bit 11 spectator)
    {
        const unsigned base = ((tid & ~255u) << 4) | (tid & 255u);
#pragma unroll
        for (int j = 0; j < 16; j++) a[j] = tile[base | (j << 8)];
        apply_rot<0>(a, rot_for(param, LAYER, 8));
        apply_rot<1>(a, rot_for(param, LAYER, 9));
        apply_rot<2>(a, rot_for(param, LAYER, 10));
#pragma unroll
        for (int j = 0; j < 16; j++) tile[base | (j << 8)] = a[j];
    }
    __syncthreads();

    // store with both CNOT sublayers folded in as a gather permutation:
    // odd sublayer targets bits {0,2,4,6,8} (mask 0x155), controls = bit above;
    // even sublayer targets bits {1,3,5,7,9} (mask 0x2AA), controls = bit above.
    for (unsigned l = tid; l < TILE; l += THREADS) {
        unsigned m = l ^ ((l >> 1) & 0x155u);
        m ^= (m >> 1) & 0x2AAu;
        d_state[gbase + l] = tile[m];
    }
}

// ---------------- pass B: tile = global bits {0,1} U {10..20} (gates on 11..20) -------
__device__ __forceinline__ unsigned pb_gidx(unsigned l, unsigned blk) {
    // smem bits 0,1 -> global 0,1 ; smem bits 2..12 -> global 10..20 ; block -> global 2..9
    return ((l >> 2) << 10) | (blk << 2) | (l & 3u);
}

template<int LAYER, bool LAST>
__global__ void __launch_bounds__(THREADS)
passB_kernel(const float* __restrict__ param) {
    extern __shared__ float2 tile[];
    const unsigned tid = threadIdx.x;
    const unsigned blk = blockIdx.x;
    float2 a[16];

    // round 1: smem bits 3-6 = global bits 11-14, straight from global
    {
        const unsigned base = ((tid & ~7u) << 4) | (tid & 7u);
#pragma unroll
        for (int j = 0; j < 16; j++) a[j] = d_state[pb_gidx(base | (j << 3), blk)];
        apply_rot<0>(a, rot_for(param, LAYER, 11));
        apply_rot<1>(a, rot_for(param, LAYER, 12));
        apply_rot<2>(a, rot_for(param, LAYER, 13));
        apply_rot<3>(a, rot_for(param, LAYER, 14));
#pragma unroll
        for (int j = 0; j < 16; j++) tile[base | (j << 3)] = a[j];
    }
    __syncthreads();

    // round 2: smem bits 7-10 = global bits 15-18
    {
        const unsigned base = ((tid & ~127u) << 4) | (tid & 127u);
#pragma unroll
        for (int j = 0; j < 16; j++) a[j] = tile[base | (j << 7)];
        apply_rot<0>(a, rot_for(param, LAYER, 15));
        apply_rot<1>(a, rot_for(param, LAYER, 16));
        apply_rot<2>(a, rot_for(param, LAYER, 17));
        apply_rot<3>(a, rot_for(param, LAYER, 18));
#pragma unroll
        for (int j = 0; j < 16; j++) tile[base | (j << 7)] = a[j];
    }
    __syncthreads();

    // round 3: smem bits {0,1,11,12}; gates on smem 11,12 = global 19,20
    {
        const unsigned base = tid << 2;
#pragma unroll
        for (int j = 0; j < 16; j++)
            a[j] = tile[base | (unsigned)(j & 3) | ((unsigned)(j >> 2) << 11)];
        apply_rot<2>(a, rot_for(param, LAYER, 19));
        apply_rot<3>(a, rot_for(param, LAYER, 20));

        if (LAST) {
            // Final layer: CNOT permutation preserves bit 0 and is a bijection, so
            // sum_{bit0=0} |amp|^2 can be taken straight from the registers.
            float acc = 0.f;
#pragma unroll
            for (int j = 0; j < 16; j += 2)           // j&1==0 -> l bit0 == 0
                acc += a[j].x * a[j].x + a[j].y * a[j].y;
#pragma unroll
            for (int o = 16; o > 0; o >>= 1)
                acc += __shfl_xor_sync(0xffffffffu, acc, o);
            __syncthreads();
            float* red = reinterpret_cast<float*>(tile);
            if ((tid & 31u) == 0) red[tid >> 5] = acc;
            __syncthreads();
            if (tid == 0) {
                float v = 0.f;
                for (int w = 0; w < 16; w++) v += red[w];
                d_partials[blk] = v;
            }
            return;
        }
#pragma unroll
        for (int j = 0; j < 16; j++)
            tile[base | (unsigned)(j & 3) | ((unsigned)(j >> 2) << 11)] = a[j];
    }
    __syncthreads();

    // store with CNOT fold: odd targets smem {2,4,6,8,10} (0x554),
    // even targets smem {3,5,7,9,11} (0xAA8)
    for (unsigned l = tid; l < TILE; l += THREADS) {
        unsigned m = l ^ ((l >> 1) & 0x554u);
        m ^= (m >> 1) & 0xAA8u;
        d_state[pb_gidx(l, blk)] = tile[m];
    }
}

__global__ void reduce_kernel(float* __restrict__ out) {
    __shared__ double sb[NBLK];
    const int tid = threadIdx.x;
    sb[tid] = (double)d_partials[tid];
    __syncthreads();
    for (int o = NBLK / 2; o > 0; o >>= 1) {
        if (tid < o) sb[tid] += sb[tid + o];
        __syncthreads();
    }
    if (tid == 0) out[0] = (float)sb[0];
}

extern "C" void kernel_launch(void* const* d_in, const int* in_sizes, int n_in,
                              void* d_out, int out_size) {
    const float* feat  = (const float*)d_in[0];
    const float* param = (const float*)d_in[1];

    cudaFuncSetAttribute(passA_kernel<0, true >, cudaFuncAttributeMaxDynamicSharedMemorySize, SMEMB);
    cudaFuncSetAttribute(passA_kernel<1, false>, cudaFuncAttributeMaxDynamicSharedMemorySize, SMEMB);
    cudaFuncSetAttribute(passA_kernel<2, false>, cudaFuncAttributeMaxDynamicSharedMemorySize, SMEMB);
    cudaFuncSetAttribute(passB_kernel<0, false>, cudaFuncAttributeMaxDynamicSharedMemorySize, SMEMB);
    cudaFuncSetAttribute(passB_kernel<1, false>, cudaFuncAttributeMaxDynamicSharedMemorySize, SMEMB);
    cudaFuncSetAttribute(passB_kernel<2, true >, cudaFuncAttributeMaxDynamicSharedMemorySize, SMEMB);

    passA_kernel<0, true ><<<NBLK, THREADS, SMEMB>>>(feat, param);
    passB_kernel<0, false><<<NBLK, THREADS, SMEMB>>>(param);
    passA_kernel<1, false><<<NBLK, THREADS, SMEMB>>>(feat, param);
    passB_kernel<1, false><<<NBLK, THREADS, SMEMB>>>(param);
    passA_kernel<2, false><<<NBLK, THREADS, SMEMB>>>(feat, param);
    passB_kernel<2, true ><<<NBLK, THREADS, SMEMB>>>(param);
    reduce_kernel<<<1, NBLK>>>((float*)d_out);
}

// round 3
// speedup vs baseline: 1.1447x; 1.1447x over previous
#include <cuda_runtime.h>
#include <math.h>

// 21-qubit / 3-layer QNN statevector sim. State in "pair format":
//   d_state[h] = float4(re(2h), re(2h+1), im(2h), im(2h+1))   (h = 20-bit pair idx)
// amp bit k <-> qubit (20-k); amp bit 0 is the float4 lane; pair bit k = amp bit k+1.
// Per layer: Rot every qubit; CNOT targets odd amp bits {1..19} (ctrl bit above);
// then even amp bits {0..18}. Split: pass A = gates on amp bits 0..10,
// pass B = amp bits 11..20 + CNOT targets {10..19}. CNOT sublayers fold into one
// XOR-gather permutation applied at each pass's store.

#define NQ      21
#define NPAIR   (1u << 20)
#define THREADS 512
#define TILEP   4096               // pairs per block tile
#define SMEMB   (TILEP * 16)       // 64 KB
#define NBLK    256

typedef unsigned long long u64;

__device__ float4 d_state[NPAIR];

struct Gate2 { u64 p, q, mq, r, mr, s, ms; };   // f32x2-duplicated coefficients
__device__ Gate2 d_gates[3][NQ];                // [layer][amp bit]

__device__ __forceinline__ u64 fma2(u64 a, u64 b, u64 c) {
    u64 d; asm("fma.rn.f32x2 %0,%1,%2,%3;" : "=l"(d) : "l"(a), "l"(b), "l"(c)); return d;
}
__device__ __forceinline__ u64 mul2(u64 a, u64 b) {
    u64 d; asm("mul.rn.f32x2 %0,%1,%2;" : "=l"(d) : "l"(a), "l"(b)); return d;
}
__device__ __forceinline__ float flo(u64 v) { return __uint_as_float((unsigned)v); }
__device__ __forceinline__ float fhi(u64 v) { return __uint_as_float((unsigned)(v >> 32)); }
__device__ __forceinline__ u64 fpack(float a, float b) {
    return (u64)__float_as_uint(a) | ((u64)__float_as_uint(b) << 32);
}
__device__ __forceinline__ unsigned sw(unsigned l) { return l ^ ((l >> 3) & 7u); }

// ---------- gate precompute (once per launch) + output zero ----------
__global__ void prep_gates(const float* __restrict__ param, float* __restrict__ out) {
    int t = threadIdx.x;
    if (t == 0) out[0] = 0.f;
    if (t >= 3 * NQ) return;
    int layer = t / NQ, bit = t % NQ, qubit = 20 - bit;
    const float* pp = param + (layer * NQ + qubit) * 3;
    float phi = pp[0], th = pp[1], om = pp[2];
    float s, c;   sincosf(0.5f * th, &s, &c);
    float sa, ca; sincosf(0.5f * (phi + om), &sa, &ca);
    float sb, cb; sincosf(0.5f * (phi - om), &sb, &cb);
    // u00=(p,q)  u01=(r,s)  u10=(-r,s)  u11=(p,-q)
    float p = ca * c, q = -sa * c, r = -cb * s, sv = -sb * s;
    Gate2 g;
    g.p  = fpack(p, p);    g.q  = fpack(q, q);   g.mq = fpack(-q, -q);
    g.r  = fpack(r, r);    g.mr = fpack(-r, -r);
    g.s  = fpack(sv, sv);  g.ms = fpack(-sv, -sv);
    d_gates[layer][bit] = g;
}

// Vector gate pairing register indices j, j|S (each reg = 2 amps along amp bit 0).
template<int S>
__device__ __forceinline__ void vgate(u64 re[8], u64 im[8], const Gate2 g) {
#pragma unroll
    for (int j = 0; j < 8; j++) {
        if (j & S) continue;
        const int j1 = j | S;
        u64 xr = re[j], xi = im[j], yr = re[j1], yi = im[j1];
        u64 nr0 = fma2(g.ms, yi, fma2(g.r,  yr, fma2(g.mq, xi, mul2(g.p,  xr))));
        u64 ni0 = fma2(g.r,  yi, fma2(g.s,  yr, fma2(g.p,  xi, mul2(g.q,  xr))));
        u64 nr1 = fma2(g.q,  yi, fma2(g.p,  yr, fma2(g.ms, xi, mul2(g.mr, xr))));
        u64 ni1 = fma2(g.p,  yi, fma2(g.mq, yr, fma2(g.mr, xi, mul2(g.s,  xr))));
        re[j] = nr0; im[j] = ni0; re[j1] = nr1; im[j1] = ni1;
    }
}

// Scalar gate on amp bit 0 (inside the f32x2 lane).
__device__ __forceinline__ void sgate(u64 re[8], u64 im[8], const Gate2 g) {
    const float p = flo(g.p), q = flo(g.q), r = flo(g.r), s = flo(g.s);
#pragma unroll
    for (int j = 0; j < 8; j++) {
        float xr = flo(re[j]), yr = fhi(re[j]), xi = flo(im[j]), yi = fhi(im[j]);
        float nr0 =  p * xr - q * xi + r * yr - s * yi;
        float ni0 =  q * xr + p * xi + s * yr + r * yi;
        float nr1 = -r * xr - s * xi + p * yr + q * yi;
        float ni1 =  s * xr - r * xi - q * yr + p * yi;
        re[j] = fpack(nr0, nr1); im[j] = fpack(ni0, ni1);
    }
}

__device__ __forceinline__ float4 packf4(u64 r, u64 i) {
    return make_float4(flo(r), fhi(r), flo(i), fhi(i));
}
__device__ __forceinline__ void unpackf4(float4 v, u64& r, u64& i) {
    r = fpack(v.x, v.y); i = fpack(v.z, v.w);
}

// ---------------- pass A: tile = pair bits 0..11 (amp bits 0..12) ----------------
template<int LAYER, bool FIRST>
__global__ void __launch_bounds__(THREADS, 2)
passA_kernel(const float* __restrict__ feat) {
    extern __shared__ float4 sm[];
    const unsigned t  = threadIdx.x;
    const unsigned gp = blockIdx.x << 12;
    u64 re[8], im[8];

    // r1: l = t | (j<<9) — lane-consecutive global; gates amp0 (scalar) + amp10 (j bit0)
#pragma unroll
    for (int j = 0; j < 8; j++) {
        unsigned l = t | (j << 9);
        if (FIRST) {
            float2 fv = reinterpret_cast<const float2*>(feat)[gp | l];
            re[j] = fpack(fv.x, fv.y); im[j] = 0ull;
        } else {
            unpackf4(d_state[gp | l], re[j], im[j]);
        }
    }
    sgate(re, im, d_gates[LAYER][0]);
    vgate<1>(re, im, d_gates[LAYER][10]);
#pragma unroll
    for (int j = 0; j < 8; j++) { unsigned l = t | (j << 9); sm[sw(l)] = packf4(re[j], im[j]); }
    __syncthreads();

    // r2: l = (t<<3) | j — gates amps 1,2,3
    {
        const unsigned base = t << 3;
#pragma unroll
        for (int j = 0; j < 8; j++) unpackf4(sm[sw(base | j)], re[j], im[j]);
        vgate<1>(re, im, d_gates[LAYER][1]);
        vgate<2>(re, im, d_gates[LAYER][2]);
        vgate<4>(re, im, d_gates[LAYER][3]);
#pragma unroll
        for (int j = 0; j < 8; j++) sm[sw(base | j)] = packf4(re[j], im[j]);
    }
    __syncthreads();

    // r3: l = (t&7) | ((t>>3)<<6) | (j<<3) — gates amps 4,5,6
    {
        const unsigned base = (t & 7u) | ((t >> 3) << 6);
#pragma unroll
        for (int j = 0; j < 8; j++) unpackf4(sm[sw(base | (j << 3))], re[j], im[j]);
        vgate<1>(re, im, d_gates[LAYER][4]);
        vgate<2>(re, im, d_gates[LAYER][5]);
        vgate<4>(re, im, d_gates[LAYER][6]);
#pragma unroll
        for (int j = 0; j < 8; j++) sm[sw(base | (j << 3))] = packf4(re[j], im[j]);
    }
    __syncthreads();

    // r4: l = (t&63) | ((t>>6)<<9) | (j<<6) — gates amps 7,8,9
    {
        const unsigned base = (t & 63u) | ((t >> 6) << 9);
#pragma unroll
        for (int j = 0; j < 8; j++) unpackf4(sm[sw(base | (j << 6))], re[j], im[j]);
        vgate<1>(re, im, d_gates[LAYER][7]);
        vgate<2>(re, im, d_gates[LAYER][8]);
        vgate<4>(re, im, d_gates[LAYER][9]);
#pragma unroll
        for (int j = 0; j < 8; j++) sm[sw(base | (j << 6))] = packf4(re[j], im[j]);
    }
    __syncthreads();

    // gather store: CNOT perm (pair bits: even-amp targets 0xAA then odd-amp 0x155)
    // + lane swap for amp-bit-0 target (ctrl = amp bit1 = h bit0). Coalesced store.
#pragma unroll
    for (int it = 0; it < 8; it++) {
        unsigned h = t | (it << 9);
        unsigned m = h ^ ((h >> 1) & 0xAAu);
        m ^= (m >> 1) & 0x155u;
        float4 v = sm[sw(m)];
        d_state[gp | h] = (h & 1u) ? make_float4(v.y, v.x, v.w, v.z) : v;
    }
}

// ---------------- pass B: tile = amp bits {0,1} U {10..20} ----------------
// local pair bit 0 -> global pair bit 0 (amp 1); blk -> g bits 1..8 (amps 2..9);
// local bits 1..11 -> g bits 9..19 (amps 10..20).
__device__ __forceinline__ unsigned gpair(unsigned l, unsigned blk) {
    return (l & 1u) | (blk << 1) | ((l >> 1) << 9);
}

template<int LAYER, bool LAST>
__global__ void __launch_bounds__(THREADS, 2)
passB_kernel(float* __restrict__ out) {
    extern __shared__ float4 sm[];
    const unsigned t = threadIdx.x;
    const unsigned blk = blockIdx.x;
    u64 re[8], im[8];

    // r1: l = (t&3) | ((t>>2)<<5) | (j<<2) — global load; gates amps 11,12,13
    {
        const unsigned base = (t & 3u) | ((t >> 2) << 5);
#pragma unroll
        for (int j = 0; j < 8; j++)
            unpackf4(d_state[gpair(base | (j << 2), blk)], re[j], im[j]);
        vgate<1>(re, im, d_gates[LAYER][11]);
        vgate<2>(re, im, d_gates[LAYER][12]);
        vgate<4>(re, im, d_gates[LAYER][13]);
#pragma unroll
        for (int j = 0; j < 8; j++) sm[sw(base | (j << 2))] = packf4(re[j], im[j]);
    }
    __syncthreads();

    // r2: l = (t&31) | ((t>>5)<<8) | (j<<5) — gates amps 14,15,16
    {
        const unsigned base = (t & 31u) | ((t >> 5) << 8);
#pragma unroll
        for (int j = 0; j < 8; j++) unpackf4(sm[sw(base | (j << 5))], re[j], im[j]);
        vgate<1>(re, im, d_gates[LAYER][14]);
        vgate<2>(re, im, d_gates[LAYER][15]);
        vgate<4>(re, im, d_gates[LAYER][16]);
#pragma unroll
        for (int j = 0; j < 8; j++) sm[sw(base | (j << 5))] = packf4(re[j], im[j]);
    }
    __syncthreads();

    // r3: l = (t&255) | ((t>>8)<<11) | (j<<8) — gates amps 17,18,19
    {
        const unsigned base = (t & 255u) | ((t >> 8) << 11);
#pragma unroll
        for (int j = 0; j < 8; j++) unpackf4(sm[sw(base | (j << 8))], re[j], im[j]);
        vgate<1>(re, im, d_gates[LAYER][17]);
        vgate<2>(re, im, d_gates[LAYER][18]);
        vgate<4>(re, im, d_gates[LAYER][19]);
#pragma unroll
        for (int j = 0; j < 8; j++) sm[sw(base | (j << 8))] = packf4(re[j], im[j]);
    }
    __syncthreads();

    // r4: l = t | (j<<9) — gate amp 20 (local bit 11 = j bit 2)
    {
#pragma unroll
        for (int j = 0; j < 8; j++) unpackf4(sm[sw(t | (j << 9))], re[j], im[j]);
        vgate<4>(re, im, d_gates[LAYER][20]);

        if (LAST) {
            // Pass-B CNOT perm is a bijection not touching amp bit 0 -> skip it;
            // sum |amp|^2 over amp bit0 == 0 (lo lanes) straight from registers.
            float acc = 0.f;
#pragma unroll
            for (int j = 0; j < 8; j++) {
                float rr = flo(re[j]), ii = flo(im[j]);
                acc += rr * rr + ii * ii;
            }
#pragma unroll
            for (int o = 16; o > 0; o >>= 1)
                acc += __shfl_xor_sync(0xffffffffu, acc, o);
            __syncthreads();                      // sm reads done before reuse
            float* red = reinterpret_cast<float*>(sm);
            if ((t & 31u) == 0) red[t >> 5] = acc;
            __syncthreads();
            if (t == 0) {
                float v = 0.f;
#pragma unroll
                for (int w = 0; w < THREADS / 32; w++) v += red[w];
                atomicAdd(out, v);
            }
            return;
        }
#pragma unroll
        for (int j = 0; j < 8; j++) sm[sw(t | (j << 9))] = packf4(re[j], im[j]);
    }
    __syncthreads();

    // gather store: even-amp targets {10..18} = local 0x2AA, then odd {11..19} = 0x554
#pragma unroll
    for (int it = 0; it < 8; it++) {
        unsigned h = t | (it << 9);
        unsigned m = h ^ ((h >> 1) & 0x2AAu);
        m ^= (m >> 1) & 0x554u;
        d_state[gpair(h, blk)] = sm[sw(m)];
    }
}

extern "C" void kernel_launch(void* const* d_in, const int* in_sizes, int n_in,
                              void* d_out, int out_size) {
    const float* feat  = (const float*)d_in[0];
    const float* param = (const float*)d_in[1];
    float* out = (float*)d_out;

    cudaFuncSetAttribute(passA_kernel<0, true >, cudaFuncAttributeMaxDynamicSharedMemorySize, SMEMB);
    cudaFuncSetAttribute(passA_kernel<1, false>, cudaFuncAttributeMaxDynamicSharedMemorySize, SMEMB);
    cudaFuncSetAttribute(passA_kernel<2, false>, cudaFuncAttributeMaxDynamicSharedMemorySize, SMEMB);
    cudaFuncSetAttribute(passB_kernel<0, false>, cudaFuncAttributeMaxDynamicSharedMemorySize, SMEMB);
    cudaFuncSetAttribute(passB_kernel<1, false>, cudaFuncAttributeMaxDynamicSharedMemorySize, SMEMB);
    cudaFuncSetAttribute(passB_kernel<2, true >, cudaFuncAttributeMaxDynamicSharedMemorySize, SMEMB);

    prep_gates<<<1, 64>>>(param, out);
    passA_kernel<0, true ><<<NBLK, THREADS, SMEMB>>>(feat);
    passB_kernel<0, false><<<NBLK, THREADS, SMEMB>>>(out);
    passA_kernel<1, false><<<NBLK, THREADS, SMEMB>>>(feat);
    passB_kernel<1, false><<<NBLK, THREADS, SMEMB>>>(out);
    passA_kernel<2, false><<<NBLK, THREADS, SMEMB>>>(feat);
    passB_kernel<2, true ><<<NBLK, THREADS, SMEMB>>>(out);
}

// round 4
// speedup vs baseline: 1.2169x; 1.0631x over previous
#include <cuda_runtime.h>
#include <math.h>

// 21-qubit / 3-layer QNN statevector sim. State in "pair format":
//   d_state[h] = float4(re(2h), re(2h+1), im(2h), im(2h+1)),  h = 20-bit pair idx.
// amp bit k <-> qubit (20-k); amp bit 0 = float4 lane; pair bit k = amp bit k+1.
// Per layer: Rot all qubits; CNOT targets odd amp bits (ctrl above); then even.
// passA: Rot amps 0..12 + CNOT targets 0..9 (perm on pair bits 0..8 + lane swap).
// passB: Rot amps 13..20 + CNOT targets 10..19 (perm on local bits 1..10).
// The CNOT permutation is applied as an INVERSE perm at the final store round
// (store register value of local l to h = m^-1(l)) — no extra smem trip.

#define NQ      21
#define NPAIR   (1u << 20)
#define THREADS 512
#define TILEP   4096
#define SMEMB   (TILEP * 16)       // 64 KB
#define NBLK    256

typedef unsigned long long u64;

__device__ float4 d_state[NPAIR];

struct Gate2 { u64 p, q, mq, r, mr, s, ms; };
__device__ Gate2 d_gates[3][NQ];

__device__ __forceinline__ u64 fma2(u64 a, u64 b, u64 c) {
    u64 d; asm("fma.rn.f32x2 %0,%1,%2,%3;" : "=l"(d) : "l"(a), "l"(b), "l"(c)); return d;
}
__device__ __forceinline__ u64 mul2(u64 a, u64 b) {
    u64 d; asm("mul.rn.f32x2 %0,%1,%2;" : "=l"(d) : "l"(a), "l"(b)); return d;
}
__device__ __forceinline__ float flo(u64 v) { return __uint_as_float((unsigned)v); }
__device__ __forceinline__ float fhi(u64 v) { return __uint_as_float((unsigned)(v >> 32)); }
__device__ __forceinline__ u64 fpack(float a, float b) {
    return (u64)__float_as_uint(a) | ((u64)__float_as_uint(b) << 32);
}
__device__ __forceinline__ unsigned sw(unsigned l) { return l ^ ((l >> 3) & 7u); }

__global__ void prep_gates(const float* __restrict__ param, float* __restrict__ out) {
    int t = threadIdx.x;
    if (t == 0) out[0] = 0.f;
    if (t >= 3 * NQ) return;
    int layer = t / NQ, bit = t % NQ, qubit = 20 - bit;
    const float* pp = param + (layer * NQ + qubit) * 3;
    float phi = pp[0], th = pp[1], om = pp[2];
    float s, c;   sincosf(0.5f * th, &s, &c);
    float sa, ca; sincosf(0.5f * (phi + om), &sa, &ca);
    float sb, cb; sincosf(0.5f * (phi - om), &sb, &cb);
    // u00=(p,q)  u01=(r,s)  u10=(-r,s)  u11=(p,-q)
    float p = ca * c, q = -sa * c, r = -cb * s, sv = -sb * s;
    Gate2 g;
    g.p  = fpack(p, p);    g.q  = fpack(q, q);   g.mq = fpack(-q, -q);
    g.r  = fpack(r, r);    g.mr = fpack(-r, -r);
    g.s  = fpack(sv, sv);  g.ms = fpack(-sv, -sv);
    d_gates[layer][bit] = g;
}

template<int S>
__device__ __forceinline__ void vgate(u64 re[8], u64 im[8], const Gate2 g) {
#pragma unroll
    for (int j = 0; j < 8; j++) {
        if (j & S) continue;
        const int j1 = j | S;
        u64 xr = re[j], xi = im[j], yr = re[j1], yi = im[j1];
        u64 nr0 = fma2(g.ms, yi, fma2(g.r,  yr, fma2(g.mq, xi, mul2(g.p,  xr))));
        u64 ni0 = fma2(g.r,  yi, fma2(g.s,  yr, fma2(g.p,  xi, mul2(g.q,  xr))));
        u64 nr1 = fma2(g.q,  yi, fma2(g.p,  yr, fma2(g.ms, xi, mul2(g.mr, xr))));
        u64 ni1 = fma2(g.p,  yi, fma2(g.mq, yr, fma2(g.mr, xi, mul2(g.s,  xr))));
        re[j] = nr0; im[j] = ni0; re[j1] = nr1; im[j1] = ni1;
    }
}

__device__ __forceinline__ void sgate(u64 re[8], u64 im[8], const Gate2 g) {
    const float p = flo(g.p), q = flo(g.q), r = flo(g.r), s = flo(g.s);
#pragma unroll
    for (int j = 0; j < 8; j++) {
        float xr = flo(re[j]), yr = fhi(re[j]), xi = flo(im[j]), yi = fhi(im[j]);
        float nr0 =  p * xr - q * xi + r * yr - s * yi;
        float ni0 =  q * xr + p * xi + s * yr + r * yi;
        float nr1 = -r * xr - s * xi + p * yr + q * yi;
        float ni1 =  s * xr - r * xi - q * yr + p * yi;
        re[j] = fpack(nr0, nr1); im[j] = fpack(ni0, ni1);
    }
}

__device__ __forceinline__ float4 packf4(u64 r, u64 i) {
    return make_float4(flo(r), fhi(r), flo(i), fhi(i));
}
__device__ __forceinline__ void unpackf4(float4 v, u64& r, u64& i) {
    r = fpack(v.x, v.y); i = fpack(v.z, v.w);
}

// ---------------- pass A: tile = pair bits 0..11 (amps 0..12) ----------------
template<int LAYER, bool FIRST>
__global__ void __launch_bounds__(THREADS, 2)
passA_kernel(const float* __restrict__ feat) {
    extern __shared__ float4 sm[];
    const unsigned t  = threadIdx.x;
    const unsigned gp = blockIdx.x << 12;
    u64 re[8], im[8];

    // r1 (global): l = t | (j<<9); gates: amp0 (scalar) + amps 10,11,12 (j bits)
#pragma unroll
    for (int j = 0; j < 8; j++) {
        unsigned l = t | (j << 9);
        if (FIRST) {
            float2 fv = reinterpret_cast<const float2*>(feat)[gp | l];
            re[j] = fpack(fv.x, fv.y); im[j] = 0ull;
        } else {
            unpackf4(d_state[gp | l], re[j], im[j]);
        }
    }
    sgate(re, im, d_gates[LAYER][0]);
    vgate<1>(re, im, d_gates[LAYER][10]);
    vgate<2>(re, im, d_gates[LAYER][11]);
    vgate<4>(re, im, d_gates[LAYER][12]);
#pragma unroll
    for (int j = 0; j < 8; j++) sm[sw(t | (j << 9))] = packf4(re[j], im[j]);
    __syncthreads();

    // r2: l = (t<<3) | j ; gates amps 1,2,3
    {
        const unsigned base = t << 3;
#pragma unroll
        for (int j = 0; j < 8; j++) unpackf4(sm[sw(base | j)], re[j], im[j]);
        vgate<1>(re, im, d_gates[LAYER][1]);
        vgate<2>(re, im, d_gates[LAYER][2]);
        vgate<4>(re, im, d_gates[LAYER][3]);
#pragma unroll
        for (int j = 0; j < 8; j++) sm[sw(base | j)] = packf4(re[j], im[j]);
    }
    __syncthreads();

    // r3: l = (t&7) | ((t>>3)<<6) | (j<<3) ; gates amps 4,5,6
    {
        const unsigned base = (t & 7u) | ((t >> 3) << 6);
#pragma unroll
        for (int j = 0; j < 8; j++) unpackf4(sm[sw(base | (j << 3))], re[j], im[j]);
        vgate<1>(re, im, d_gates[LAYER][4]);
        vgate<2>(re, im, d_gates[LAYER][5]);
        vgate<4>(re, im, d_gates[LAYER][6]);
#pragma unroll
        for (int j = 0; j < 8; j++) sm[sw(base | (j << 3))] = packf4(re[j], im[j]);
    }
    __syncthreads();

    // r4: l = (t&63) | ((t>>6)<<9) | (j<<6) ; gates amps 7,8,9; then CNOT perm
    // folded into the store: h = m^-1(l), lane swap if h&1.
    {
        const unsigned base = (t & 63u) | ((t >> 6) << 9);
#pragma unroll
        for (int j = 0; j < 8; j++) unpackf4(sm[sw(base | (j << 6))], re[j], im[j]);
        vgate<1>(re, im, d_gates[LAYER][7]);
        vgate<2>(re, im, d_gates[LAYER][8]);
        vgate<4>(re, im, d_gates[LAYER][9]);
#pragma unroll
        for (int j = 0; j < 8; j++) {
            unsigned l = base | (j << 6);
            unsigned u = l ^ ((l >> 1) & 0x155u);
            unsigned h = u ^ ((u >> 1) & 0xAAu);
            float4 v = packf4(re[j], im[j]);
            d_state[gp | h] = (h & 1u) ? make_float4(v.y, v.x, v.w, v.z) : v;
        }
    }
}

// ---------------- pass B: tile = amp bits {0,1} U {10..20} ----------------
// local bit 0 -> global pair bit 0 (amp1 spectator); blk -> g bits 1..8;
// local bits 1..11 -> g bits 9..19 (amps 10..20).
__device__ __forceinline__ unsigned gpair(unsigned l, unsigned blk) {
    return (l & 1u) | (blk << 1) | ((l >> 1) << 9);
}

template<int LAYER, bool LAST>
__global__ void __launch_bounds__(THREADS, 2)
passB_kernel(float* __restrict__ out) {
    extern __shared__ float4 sm[];
    const unsigned t = threadIdx.x;
    const unsigned blk = blockIdx.x;
    u64 re[8], im[8];

    // r1 (global): l = (t&15) | ((t>>4)<<7) | (j<<4) ; gates amps 13,14,15
    {
        const unsigned base = (t & 15u) | ((t >> 4) << 7);
#pragma unroll
        for (int j = 0; j < 8; j++)
            unpackf4(d_state[gpair(base | (j << 4), blk)], re[j], im[j]);
        vgate<1>(re, im, d_gates[LAYER][13]);
        vgate<2>(re, im, d_gates[LAYER][14]);
        vgate<4>(re, im, d_gates[LAYER][15]);
#pragma unroll
        for (int j = 0; j < 8; j++) sm[sw(base | (j << 4))] = packf4(re[j], im[j]);
    }
    __syncthreads();

    // r2: l = t | (j<<9) ; gates amps 18,19,20
    {
#pragma unroll
        for (int j = 0; j < 8; j++) unpackf4(sm[sw(t | (j << 9))], re[j], im[j]);
        vgate<1>(re, im, d_gates[LAYER][18]);
        vgate<2>(re, im, d_gates[LAYER][19]);
        vgate<4>(re, im, d_gates[LAYER][20]);
#pragma unroll
        for (int j = 0; j < 8; j++) sm[sw(t | (j << 9))] = packf4(re[j], im[j]);
    }
    __syncthreads();

    // r3: l = (t&127) | ((t>>7)<<10) | (j<<7) ; gates amps 16,17; perm-store or reduce
    {
        const unsigned base = (t & 127u) | ((t >> 7) << 10);
#pragma unroll
        for (int j = 0; j < 8; j++) unpackf4(sm[sw(base | (j << 7))], re[j], im[j]);
        vgate<1>(re, im, d_gates[LAYER][16]);
        vgate<2>(re, im, d_gates[LAYER][17]);

        if (LAST) {
            // Perm is a bijection not touching amp bit 0 -> skip it; sum lo lanes.
            float acc = 0.f;
#pragma unroll
            for (int j = 0; j < 8; j++) {
                float rr = flo(re[j]), ii = flo(im[j]);
                acc += rr * rr + ii * ii;
            }
#pragma unroll
            for (int o = 16; o > 0; o >>= 1)
                acc += __shfl_xor_sync(0xffffffffu, acc, o);
            __syncthreads();
            float* red = reinterpret_cast<float*>(sm);
            if ((t & 31u) == 0) red[t >> 5] = acc;
            __syncthreads();
            if (t == 0) {
                float v = 0.f;
#pragma unroll
                for (int w = 0; w < THREADS / 32; w++) v += red[w];
                atomicAdd(out, v);
            }
            return;
        }
#pragma unroll
        for (int j = 0; j < 8; j++) {
            unsigned l = base | (j << 7);
            unsigned u = l ^ ((l >> 1) & 0x554u);
            unsigned h = u ^ ((u >> 1) & 0x2AAu);
            d_state[gpair(h, blk)] = packf4(re[j], im[j]);
        }
    }
}

extern "C" void kernel_launch(void* const* d_in, const int* in_sizes, int n_in,
                              void* d_out, int out_size) {
    const float* feat  = (const float*)d_in[0];
    const float* param = (const float*)d_in[1];
    float* out = (float*)d_out;

    cudaFuncSetAttribute(passA_kernel<0, true >, cudaFuncAttributeMaxDynamicSharedMemorySize, SMEMB);
    cudaFuncSetAttribute(passA_kernel<1, false>, cudaFuncAttributeMaxDynamicSharedMemorySize, SMEMB);
    cudaFuncSetAttribute(passA_kernel<2, false>, cudaFuncAttributeMaxDynamicSharedMemorySize, SMEMB);
    cudaFuncSetAttribute(passB_kernel<0, false>, cudaFuncAttributeMaxDynamicSharedMemorySize, SMEMB);
    cudaFuncSetAttribute(passB_kernel<1, false>, cudaFuncAttributeMaxDynamicSharedMemorySize, SMEMB);
    cudaFuncSetAttribute(passB_kernel<2, true >, cudaFuncAttributeMaxDynamicSharedMemorySize, SMEMB);

    prep_gates<<<1, 64>>>(param, out);
    passA_kernel<0, true ><<<NBLK, THREADS, SMEMB>>>(feat);
    passB_kernel<0, false><<<NBLK, THREADS, SMEMB>>>(out);
    passA_kernel<1, false><<<NBLK, THREADS, SMEMB>>>(feat);
    passB_kernel<1, false><<<NBLK, THREADS, SMEMB>>>(out);
    passA_kernel<2, false><<<NBLK, THREADS, SMEMB>>>(feat);
    passB_kernel<2, true ><<<NBLK, THREADS, SMEMB>>>(out);
}

// round 5
// speedup vs baseline: 1.3622x; 1.1194x over previous
#include <cuda_runtime.h>
#include <math.h>

// 21-qubit / 3-layer QNN statevector sim. State in "pair format":
//   d_state[h] = float4(re(2h), re(2h+1), im(2h), im(2h+1)),  h = 20-bit pair idx.
// amp bit k <-> qubit (20-k); amp bit 0 = float4 lane; pair bit k = amp bit k+1.
// passA: Rots amps 0..12 + CNOT targets 0..9 (perm + lane swap at store).
// passB: Rots amps 13..20 + CNOT targets 10..19 (perm at store).
// Rounds are collapsed using warp-shuffle gates on lane-resident pair bits:
// passA = 2 rounds (1 smem trip), passB = 2 rounds (1 smem trip).

#define NQ      21
#define NPAIR   (1u << 20)
#define THREADS 512
#define TILEP   4096
#define SMEMB   (TILEP * 16 + 1024)   // tile + gate table
#define NBLK    256

typedef unsigned long long u64;

__device__ float4 d_state[NPAIR];

struct Gate2 { u64 p, q, mq, r, mr, s, ms; };   // f32x2-duplicated coefficients
__device__ Gate2 d_gates[3][NQ];

__device__ __forceinline__ u64 fma2(u64 a, u64 b, u64 c) {
    u64 d; asm("fma.rn.f32x2 %0,%1,%2,%3;" : "=l"(d) : "l"(a), "l"(b), "l"(c)); return d;
}
__device__ __forceinline__ u64 mul2(u64 a, u64 b) {
    u64 d; asm("mul.rn.f32x2 %0,%1,%2;" : "=l"(d) : "l"(a), "l"(b)); return d;
}
__device__ __forceinline__ float flo(u64 v) { return __uint_as_float((unsigned)v); }
__device__ __forceinline__ float fhi(u64 v) { return __uint_as_float((unsigned)(v >> 32)); }
__device__ __forceinline__ u64 fpack(float a, float b) {
    return (u64)__float_as_uint(a) | ((u64)__float_as_uint(b) << 32);
}
__device__ __forceinline__ unsigned sw(unsigned l) { return l ^ ((l >> 3) & 7u); }

__global__ void prep_gates(const float* __restrict__ param, float* __restrict__ out) {
    int t = threadIdx.x;
    if (t == 0) out[0] = 0.f;
    if (t >= 3 * NQ) return;
    int layer = t / NQ, bit = t % NQ, qubit = 20 - bit;
    const float* pp = param + (layer * NQ + qubit) * 3;
    float phi = pp[0], th = pp[1], om = pp[2];
    float s, c;   sincosf(0.5f * th, &s, &c);
    float sa, ca; sincosf(0.5f * (phi + om), &sa, &ca);
    float sb, cb; sincosf(0.5f * (phi - om), &sb, &cb);
    // u00=(p,q)  u01=(r,s)  u10=(-r,s)  u11=(p,-q)
    float p = ca * c, q = -sa * c, r = -cb * s, sv = -sb * s;
    Gate2 g;
    g.p  = fpack(p, p);    g.q  = fpack(q, q);   g.mq = fpack(-q, -q);
    g.r  = fpack(r, r);    g.mr = fpack(-r, -r);
    g.s  = fpack(sv, sv);  g.ms = fpack(-sv, -sv);
    d_gates[layer][bit] = g;
}

// Paired-register gate: register indices j, j|S (each reg = 2 amps along amp bit 0).
template<int S>
__device__ __forceinline__ void vgate(u64 re[8], u64 im[8], const u64* __restrict__ g) {
    const u64 p = g[0], q = g[1], mq = g[2], r = g[3], mr = g[4], s = g[5], ms = g[6];
#pragma unroll
    for (int j = 0; j < 8; j++) {
        if (j & S) continue;
        const int j1 = j | S;
        u64 xr = re[j], xi = im[j], yr = re[j1], yi = im[j1];
        u64 nr0 = fma2(ms, yi, fma2(r,  yr, fma2(mq, xi, mul2(p,  xr))));
        u64 ni0 = fma2(r,  yi, fma2(s,  yr, fma2(p,  xi, mul2(q,  xr))));
        u64 nr1 = fma2(q,  yi, fma2(p,  yr, fma2(ms, xi, mul2(mr, xr))));
        u64 ni1 = fma2(p,  yi, fma2(mq, yr, fma2(mr, xi, mul2(s,  xr))));
        re[j] = nr0; im[j] = ni0; re[j1] = nr1; im[j1] = ni1;
    }
}

// Warp-shuffle gate on lane bit B (pair bit mapped onto lane bit B of threadIdx).
// side0: re' = p*vr - q*vi + r*wr - s*wi ; im' =  q*vr + p*vi + s*wr + r*wi
// side1: re' = p*vr + q*vi - r*wr - s*wi ; im' = -q*vr + p*vi + s*wr - r*wi
template<int B>
__device__ __forceinline__ void hgate(u64 re[8], u64 im[8], const u64* __restrict__ g) {
    const u64 p = g[0], s = g[5], ms = g[6];
    const bool hi = (threadIdx.x >> B) & 1;
    const u64 A  = hi ? g[1] : g[2];   //  q : -q
    const u64 C  = hi ? g[2] : g[1];   // -q :  q
    const u64 Bc = hi ? g[4] : g[3];   // -r :  r
#pragma unroll
    for (int j = 0; j < 8; j++) {
        u64 wr = __shfl_xor_sync(0xffffffffu, re[j], 1 << B);
        u64 wi = __shfl_xor_sync(0xffffffffu, im[j], 1 << B);
        u64 nr = fma2(ms, wi, fma2(Bc, wr, fma2(A, im[j], mul2(p, re[j]))));
        u64 ni = fma2(Bc, wi, fma2(s,  wr, fma2(p, im[j], mul2(C, re[j]))));
        re[j] = nr; im[j] = ni;
    }
}

// Scalar gate on amp bit 0 (inside the f32x2 lane).
__device__ __forceinline__ void sgate(u64 re[8], u64 im[8], const u64* __restrict__ g) {
    const float p = flo(g[0]), q = flo(g[1]), r = flo(g[3]), s = flo(g[5]);
#pragma unroll
    for (int j = 0; j < 8; j++) {
        float xr = flo(re[j]), yr = fhi(re[j]), xi = flo(im[j]), yi = fhi(im[j]);
        float nr0 =  p * xr - q * xi + r * yr - s * yi;
        float ni0 =  q * xr + p * xi + s * yr + r * yi;
        float nr1 = -r * xr - s * xi + p * yr + q * yi;
        float ni1 =  s * xr - r * xi - q * yr + p * yi;
        re[j] = fpack(nr0, nr1); im[j] = fpack(ni0, ni1);
    }
}

__device__ __forceinline__ float4 packf4(u64 r, u64 i) {
    return make_float4(flo(r), fhi(r), flo(i), fhi(i));
}
__device__ __forceinline__ void unpackf4(float4 v, u64& r, u64& i) {
    r = fpack(v.x, v.y); i = fpack(v.z, v.w);
}

// r2 layout for both passes: t0..3->l0..3, t5->l4, j->l5..7, t4->l8, t6..8->l9..11
__device__ __forceinline__ unsigned r2idx(unsigned t, unsigned j) {
    return (t & 15u) | (((t >> 5) & 1u) << 4) | (j << 5)
         | (((t >> 4) & 1u) << 8) | ((t >> 6) << 9);
}

// ---------------- pass A: tile = pair bits 0..11 (amps 0..12) ----------------
template<int LAYER, bool FIRST>
__global__ void __launch_bounds__(THREADS, 2)
passA_kernel(const float* __restrict__ feat) {
    extern __shared__ char smraw[];
    float4* sm = reinterpret_cast<float4*>(smraw);
    u64* gsm = reinterpret_cast<u64*>(smraw + TILEP * 16);
    const unsigned t  = threadIdx.x;
    const unsigned gp = blockIdx.x << 12;
    u64 re[8], im[8];

    // stage gate table: amps 0..12 = 13 gates x 7 u64
    {
        const u64* src = reinterpret_cast<const u64*>(d_gates) + (LAYER * NQ) * 7;
        if (t < 91) gsm[t] = src[t];
    }

    // r1 (global): l = t | (j<<9)
#pragma unroll
    for (int j = 0; j < 8; j++) {
        unsigned l = t | (j << 9);
        if (FIRST) {
            float2 fv = reinterpret_cast<const float2*>(feat)[gp | l];
            re[j] = fpack(fv.x, fv.y); im[j] = 0ull;
        } else {
            unpackf4(d_state[gp | l], re[j], im[j]);
        }
    }
    __syncthreads();                       // gate table visible

    sgate(re, im, gsm + 0 * 7);            // amp 0
    hgate<0>(re, im, gsm + 1 * 7);         // amp 1  (pair bit 0 = lane bit 0)
    hgate<1>(re, im, gsm + 2 * 7);         // amp 2
    hgate<2>(re, im, gsm + 3 * 7);         // amp 3
    hgate<3>(re, im, gsm + 4 * 7);         // amp 4
    hgate<4>(re, im, gsm + 5 * 7);         // amp 5
    vgate<1>(re, im, gsm + 10 * 7);        // amp 10 (pair bit 9 = j bit 0)
    vgate<2>(re, im, gsm + 11 * 7);        // amp 11
    vgate<4>(re, im, gsm + 12 * 7);        // amp 12
#pragma unroll
    for (int j = 0; j < 8; j++) sm[sw(t | (j << 9))] = packf4(re[j], im[j]);
    __syncthreads();

    // r2: l = r2idx(t,j); j = pair bits 5,6,7 (amps 6,7,8); lane bit 4 -> pair 8 (amp 9)
#pragma unroll
    for (int j = 0; j < 8; j++) unpackf4(sm[sw(r2idx(t, j))], re[j], im[j]);
    vgate<1>(re, im, gsm + 6 * 7);         // amp 6
    vgate<2>(re, im, gsm + 7 * 7);         // amp 7
    vgate<4>(re, im, gsm + 8 * 7);         // amp 8
    hgate<4>(re, im, gsm + 9 * 7);         // amp 9  (pair bit 8 = lane bit 4 here)

    // CNOT perm (targets amps 0..9) folded into the store as inverse perm:
#pragma unroll
    for (int j = 0; j < 8; j++) {
        unsigned l = r2idx(t, j);
        unsigned u = l ^ ((l >> 1) & 0x155u);
        unsigned h = u ^ ((u >> 1) & 0xAAu);
        float4 v = packf4(re[j], im[j]);
        d_state[gp | h] = (h & 1u) ? make_float4(v.y, v.x, v.w, v.z) : v;
    }
}

// ---------------- pass B: tile local bits: 0 = pair 0; 1..11 = pairs 9..19 ----------
__device__ __forceinline__ unsigned gpair(unsigned l, unsigned blk) {
    return (l & 1u) | (blk << 1) | ((l >> 1) << 9);
}

template<int LAYER, bool LAST>
__global__ void __launch_bounds__(THREADS, 2)
passB_kernel(float* __restrict__ out) {
    extern __shared__ char smraw[];
    float4* sm = reinterpret_cast<float4*>(smraw);
    u64* gsm = reinterpret_cast<u64*>(smraw + TILEP * 16);
    const unsigned t = threadIdx.x;
    const unsigned blk = blockIdx.x;
    u64 re[8], im[8];

    // stage gate table: amps 13..20 = 8 gates x 7 u64
    {
        const u64* src = reinterpret_cast<const u64*>(d_gates) + (LAYER * NQ + 13) * 7;
        if (t < 56) gsm[t] = src[t];
    }

    // r1 (global): l = t | (j<<9); j = local 9,10,11 = amps 18,19,20; lane bit 4 = local 4 = amp 13
#pragma unroll
    for (int j = 0; j < 8; j++)
        unpackf4(d_state[gpair(t | (j << 9), blk)], re[j], im[j]);
    __syncthreads();                       // gate table visible

    hgate<4>(re, im, gsm + 0 * 7);         // amp 13
    vgate<1>(re, im, gsm + 5 * 7);         // amp 18
    vgate<2>(re, im, gsm + 6 * 7);         // amp 19
    vgate<4>(re, im, gsm + 7 * 7);         // amp 20
#pragma unroll
    for (int j = 0; j < 8; j++) sm[sw(t | (j << 9))] = packf4(re[j], im[j]);
    __syncthreads();

    // r2: l = r2idx(t,j); j = local 5,6,7 = amps 14,15,16; lane bit 4 -> local 8 = amp 17
#pragma unroll
    for (int j = 0; j < 8; j++) unpackf4(sm[sw(r2idx(t, j))], re[j], im[j]);
    vgate<1>(re, im, gsm + 1 * 7);         // amp 14
    vgate<2>(re, im, gsm + 2 * 7);         // amp 15
    vgate<4>(re, im, gsm + 3 * 7);         // amp 16
    hgate<4>(re, im, gsm + 4 * 7);         // amp 17

    if (LAST) {
        // Perm (local bits 1..10) is a bijection not touching amp bit 0 -> skip;
        // sum |amp|^2 over lo lanes.
        float acc = 0.f;
#pragma unroll
        for (int j = 0; j < 8; j++) {
            float rr = flo(re[j]), ii = flo(im[j]);
            acc += rr * rr + ii * ii;
        }
#pragma unroll
        for (int o = 16; o > 0; o >>= 1)
            acc += __shfl_xor_sync(0xffffffffu, acc, o);
        __syncthreads();                   // all sm reads done before reuse
        float* red = reinterpret_cast<float*>(sm);
        if ((t & 31u) == 0) red[t >> 5] = acc;
        __syncthreads();
        if (t == 0) {
            float v = 0.f;
#pragma unroll
            for (int w = 0; w < THREADS / 32; w++) v += red[w];
            atomicAdd(out, v);
        }
        return;
    }

    // CNOT perm (targets amps 10..19 = local bits 1..10) inverse-folded into store
#pragma unroll
    for (int j = 0; j < 8; j++) {
        unsigned l = r2idx(t, j);
        unsigned u = l ^ ((l >> 1) & 0x554u);
        unsigned h = u ^ ((u >> 1) & 0x2AAu);
        d_state[gpair(h, blk)] = packf4(re[j], im[j]);
    }
}

extern "C" void kernel_launch(void* const* d_in, const int* in_sizes, int n_in,
                              void* d_out, int out_size) {
    const float* feat  = (const float*)d_in[0];
    const float* param = (const float*)d_in[1];
    float* out = (float*)d_out;

    cudaFuncSetAttribute(passA_kernel<0, true >, cudaFuncAttributeMaxDynamicSharedMemorySize, SMEMB);
    cudaFuncSetAttribute(passA_kernel<1, false>, cudaFuncAttributeMaxDynamicSharedMemorySize, SMEMB);
    cudaFuncSetAttribute(passA_kernel<2, false>, cudaFuncAttributeMaxDynamicSharedMemorySize, SMEMB);
    cudaFuncSetAttribute(passB_kernel<0, false>, cudaFuncAttributeMaxDynamicSharedMemorySize, SMEMB);
    cudaFuncSetAttribute(passB_kernel<1, false>, cudaFuncAttributeMaxDynamicSharedMemorySize, SMEMB);
    cudaFuncSetAttribute(passB_kernel<2, true >, cudaFuncAttributeMaxDynamicSharedMemorySize, SMEMB);

    prep_gates<<<1, 64>>>(param, out);
    passA_kernel<0, true ><<<NBLK, THREADS, SMEMB>>>(feat);
    passB_kernel<0, false><<<NBLK, THREADS, SMEMB>>>(out);
    passA_kernel<1, false><<<NBLK, THREADS, SMEMB>>>(feat);
    passB_kernel<1, false><<<NBLK, THREADS, SMEMB>>>(out);
    passA_kernel<2, false><<<NBLK, THREADS, SMEMB>>>(feat);
    passB_kernel<2, true ><<<NBLK, THREADS, SMEMB>>>(out);
}